// round 2
// baseline (speedup 1.0000x reference)
#include <cuda_runtime.h>
#include <cuda_bf16.h>
#include <math.h>

// Problem dims (fixed)
#define DM    1024   // d_model
#define DI    2048   // d_inner
#define DS    16     // d_state
#define DC    4      // d_conv
#define DTR   64     // dt_rank
#define NB    2      // batch
#define LL    1024   // seq len
#define NTOK  (NB*LL)        // 2048 tokens
#define XDBLC (DTR + 2*DS)   // 96

// Scratch (static device globals — allocation-free)
__device__ float g_XZ   [NTOK * 2 * DI];   // 2048 x 4096
__device__ float g_Xc   [NTOK * DI];       // 2048 x 2048 (post conv+silu)
__device__ float g_XDBL [NTOK * XDBLC];    // 2048 x 96
__device__ float g_DELTA[NTOK * DI];       // 2048 x 2048 (dt -> delta)
__device__ float g_Y    [NTOK * DI];       // 2048 x 2048 (pre out-proj)
__device__ float g_beta;

// ---------------------------------------------------------------------------
// Generic SGEMM: C[M,N] = A[M,K] * B[N,K]^T   (both row-major, arbitrary ld)
// 128x128 block tile, BK=16, 256 threads, 8x8 per thread.
// B-fragment uses interleaved columns (tx + j*16) for conflict-free LDS and
// coalesced C stores.
// ---------------------------------------------------------------------------
#define BM 128
#define BN 128
#define BK 16
__global__ __launch_bounds__(256) void sgemm_nt(
    const float* __restrict__ A, const float* __restrict__ B,
    float* __restrict__ C, int M, int N, int K, int lda, int ldb, int ldc)
{
    __shared__ float As[BK][BM];
    __shared__ float Bs[BK][BN];

    const int tid = threadIdx.x;
    const int tx = tid & 15;        // 0..15
    const int ty = tid >> 4;        // 0..15
    const int row0 = blockIdx.y * BM;
    const int col0 = blockIdx.x * BN;

    // loader mapping: lr = tid/2 (row in tile), lc = (tid&1)*8 (k offset)
    const int lr = tid >> 1;
    const int lc = (tid & 1) * 8;

    float acc[8][8];
#pragma unroll
    for (int i = 0; i < 8; i++)
#pragma unroll
        for (int j = 0; j < 8; j++) acc[i][j] = 0.f;

    for (int kt = 0; kt < K; kt += BK) {
        // load A tile (transposed into As[k][m])
        {
            int gr = row0 + lr;
            bool rok = (gr < M);
#pragma unroll
            for (int j = 0; j < 8; j++) {
                int gk = kt + lc + j;
                As[lc + j][lr] = (rok && gk < K) ? A[(long)gr * lda + gk] : 0.f;
            }
        }
        // load B tile
        {
            int gr = col0 + lr;
            bool rok = (gr < N);
#pragma unroll
            for (int j = 0; j < 8; j++) {
                int gk = kt + lc + j;
                Bs[lc + j][lr] = (rok && gk < K) ? B[(long)gr * ldb + gk] : 0.f;
            }
        }
        __syncthreads();

#pragma unroll
        for (int k = 0; k < BK; k++) {
            float ar[8], br[8];
#pragma unroll
            for (int i = 0; i < 8; i++) ar[i] = As[k][ty * 8 + i];
#pragma unroll
            for (int j = 0; j < 8; j++) br[j] = Bs[k][tx + j * 16];
#pragma unroll
            for (int i = 0; i < 8; i++)
#pragma unroll
                for (int j = 0; j < 8; j++)
                    acc[i][j] = fmaf(ar[i], br[j], acc[i][j]);
        }
        __syncthreads();
    }

#pragma unroll
    for (int i = 0; i < 8; i++) {
        int r = row0 + ty * 8 + i;
        if (r >= M) continue;
#pragma unroll
        for (int j = 0; j < 8; j++) {
            int c = col0 + tx + j * 16;
            if (c < N) C[(long)r * ldc + c] = acc[i][j];
        }
    }
}

// ---------------------------------------------------------------------------
// Causal depthwise conv (k=4) + bias + silu.  x channel d of XZ -> Xc(token,d)
// ---------------------------------------------------------------------------
__global__ void conv_silu_kernel(const float* __restrict__ XZ,
                                 const float* __restrict__ w,
                                 const float* __restrict__ cb,
                                 float* __restrict__ Xc)
{
    int idx = blockIdx.x * blockDim.x + threadIdx.x;   // over NTOK*DI
    if (idx >= NTOK * DI) return;
    int d = idx & (DI - 1);
    int token = idx >> 11;
    int b = token >> 10;
    int l = token & (LL - 1);

    float accv = cb[d];
#pragma unroll
    for (int j = 0; j < 4; j++) {
        int ll = l + j - 3;
        if (ll >= 0)
            accv = fmaf(w[d * 4 + j], XZ[((long)(b * LL + ll)) * (2 * DI) + d], accv);
    }
    float s = accv / (1.f + expf(-accv));
    Xc[idx] = s;
}

// ---------------------------------------------------------------------------
// delta = clip(softplus(dt + dt_bias), 1e-4, 20)   (in-place on g_DELTA)
// ---------------------------------------------------------------------------
__global__ void delta_kernel(float* __restrict__ DT, const float* __restrict__ dt_bias)
{
    int idx = blockIdx.x * blockDim.x + threadIdx.x;
    if (idx >= NTOK * DI) return;
    int d = idx & (DI - 1);
    float v = DT[idx] + dt_bias[d];
    float sp = (v > 30.f) ? v : log1pf(expf(v));
    DT[idx] = fminf(fmaxf(sp, 1e-4f), 20.f);
}

// ---------------------------------------------------------------------------
// beta = max(0, -min(Bm))   over XDBL[:, 64:80]
// ---------------------------------------------------------------------------
__global__ void beta_kernel(const float* __restrict__ XDBL)
{
    __shared__ float sm[1024];
    float mv = 3.0e38f;
    for (int i = threadIdx.x; i < NTOK * DS; i += 1024) {
        int token = i >> 4, n = i & 15;
        mv = fminf(mv, XDBL[token * XDBLC + DTR + n]);
    }
    sm[threadIdx.x] = mv;
    __syncthreads();
    for (int s = 512; s > 0; s >>= 1) {
        if (threadIdx.x < s) sm[threadIdx.x] = fminf(sm[threadIdx.x], sm[threadIdx.x + s]);
        __syncthreads();
    }
    if (threadIdx.x == 0) g_beta = fmaxf(0.f, -sm[0]);
}

// ---------------------------------------------------------------------------
// Selective scan. 16 lanes per sequence (n across lanes), 2 sequences / warp.
// state[n]: xc = exp(-delta*A[d,n]) * xc + (delta*x) * (Bm[n]+beta)
// y = sum_n xc*Cm[n];  Y = (y + x*D[d]) * silu(z)
// ---------------------------------------------------------------------------
__global__ __launch_bounds__(256) void scan_kernel(
    const float* __restrict__ XZ,   const float* __restrict__ XDBL,
    const float* __restrict__ DELTA,const float* __restrict__ Xc,
    const float* __restrict__ A_log,const float* __restrict__ Dv,
    float* __restrict__ Y)
{
    int gtid = blockIdx.x * blockDim.x + threadIdx.x;
    int lane = gtid & 31;
    int warp = gtid >> 5;
    int seq  = warp * 2 + (lane >> 4);   // 0..4095
    int n    = lane & 15;
    int b    = seq >> 11;
    int d    = seq & (DI - 1);

    float a    = expf(A_log[d * DS + n]);
    float beta = g_beta;
    float Dd   = Dv[d];
    float state = 0.f;
    int tokBase = b << 10;

    for (int l = 0; l < LL; l++) {
        int token = tokBase + l;
        float delta = DELTA[(long)token * DI + d];
        float x     = Xc[(long)token * DI + d];
        const float* xr = XDBL + (long)token * XDBLC;
        float Bv = xr[DTR + n] + beta;
        float Cv = xr[DTR + DS + n];
        float dA = expf(-delta * a);
        state = fmaf(dA, state, (delta * x) * Bv);
        float p = state * Cv;
        p += __shfl_xor_sync(0xffffffffu, p, 1);
        p += __shfl_xor_sync(0xffffffffu, p, 2);
        p += __shfl_xor_sync(0xffffffffu, p, 4);
        p += __shfl_xor_sync(0xffffffffu, p, 8);
        if (n == 0) {
            float z  = XZ[(long)token * (2 * DI) + DI + d];
            float sz = z / (1.f + expf(-z));
            Y[(long)token * DI + d] = (p + x * Dd) * sz;
        }
    }
}

// ---------------------------------------------------------------------------
extern "C" void kernel_launch(void* const* d_in, const int* in_sizes, int n_in,
                              void* d_out, int out_size)
{
    const float* hidden  = (const float*)d_in[0];
    const float* W_in    = (const float*)d_in[1];
    const float* conv_w  = (const float*)d_in[2];
    const float* conv_b  = (const float*)d_in[3];
    const float* W_x     = (const float*)d_in[4];
    const float* W_dt    = (const float*)d_in[5];
    const float* dt_bias = (const float*)d_in[6];
    const float* W_out   = (const float*)d_in[7];
    const float* A_log   = (const float*)d_in[8];
    const float* Dv      = (const float*)d_in[9];
    float* out = (float*)d_out;

    float *XZ, *Xc, *XDBL, *DELTA, *Y;
    cudaGetSymbolAddress((void**)&XZ,    g_XZ);
    cudaGetSymbolAddress((void**)&Xc,    g_Xc);
    cudaGetSymbolAddress((void**)&XDBL,  g_XDBL);
    cudaGetSymbolAddress((void**)&DELTA, g_DELTA);
    cudaGetSymbolAddress((void**)&Y,     g_Y);

    // 1) xz = hidden @ W_in^T          (2048 x 4096, K=1024)
    sgemm_nt<<<dim3((2 * DI) / BN, NTOK / BM), 256>>>(
        hidden, W_in, XZ, NTOK, 2 * DI, DM, DM, DM, 2 * DI);

    // 2) causal conv + silu -> Xc
    conv_silu_kernel<<<(NTOK * DI) / 256, 256>>>(XZ, conv_w, conv_b, Xc);

    // 3) x_dbl = Xc @ W_x^T            (2048 x 96, K=2048)
    sgemm_nt<<<dim3(1, NTOK / BM), 256>>>(
        Xc, W_x, XDBL, NTOK, XDBLC, DI, DI, DI, XDBLC);

    // 4) dt = x_dbl[:, :64] @ W_dt^T   (2048 x 2048, K=64)
    sgemm_nt<<<dim3(DI / BN, NTOK / BM), 256>>>(
        XDBL, W_dt, DELTA, NTOK, DI, DTR, XDBLC, DTR, DI);

    // 5) delta = clip(softplus(dt + bias))
    delta_kernel<<<(NTOK * DI) / 256, 256>>>(DELTA, dt_bias);

    // 6) beta reduction
    beta_kernel<<<1, 1024>>>(XDBL);

    // 7) selective scan + gating -> Y
    scan_kernel<<<(NB * DI * DS) / 256, 256>>>(XZ, XDBL, DELTA, Xc, A_log, Dv, Y);

    // 8) out = Y @ W_out^T             (2048 x 1024, K=2048)
    sgemm_nt<<<dim3(DM / BN, NTOK / BM), 256>>>(
        Y, W_out, out, NTOK, DM, DI, DI, DI, DM);
}

// round 6
// speedup vs baseline: 2.6972x; 2.6972x over previous
#include <cuda_runtime.h>
#include <cuda_bf16.h>
#include <cstdint>
#include <stdint.h>
#include <math.h>

// ---------------- problem dims (fixed) ----------------
#define DM    1024
#define DI    2048
#define DS    16
#define DTR   64
#define NB    2
#define LL    1024
#define NTOK  (NB*LL)        // 2048
#define XDBLC (DTR + 2*DS)   // 96

// ---------------- fp32 scratch ----------------
__device__ float g_XZ   [NTOK * 2 * DI];
__device__ float g_Xc   [NTOK * DI];
__device__ float g_XDBL [NTOK * XDBLC];
__device__ float g_DELTA[NTOK * DI];
__device__ float g_Y    [NTOK * DI];
__device__ float g_beta;

// ---------------- bf16 split scratch (uint4 => 16B aligned) ----------------
__device__ uint4 g_hidH [NTOK*DM/8],   g_hidL [NTOK*DM/8];
__device__ uint4 g_WinH [2*DI*DM/8],   g_WinL [2*DI*DM/8];
__device__ uint4 g_XcH  [NTOK*DI/8],   g_XcL  [NTOK*DI/8];
__device__ uint4 g_WxH  [XDBLC*DI/8],  g_WxL  [XDBLC*DI/8];
__device__ uint4 g_XdH  [NTOK*XDBLC/8],g_XdL  [NTOK*XDBLC/8];
__device__ uint4 g_WdtH [DI*DTR/8],    g_WdtL [DI*DTR/8];
__device__ uint4 g_YH   [NTOK*DI/8],   g_YL   [NTOK*DI/8];
__device__ uint4 g_WoutH[DM*DI/8],     g_WoutL[DM*DI/8];

// ---------------- helpers ----------------
__device__ __forceinline__ uint32_t smem_to_u32(const void* p) {
    uint32_t a;
    asm("{ .reg .u64 t; cvta.to.shared.u64 t, %1; cvt.u32.u64 %0, t; }" : "=r"(a) : "l"(p));
    return a;
}
// SW128-style swizzle inside a 128-rows x 128B tile: row r, byte col b
__device__ __forceinline__ uint32_t swz(uint32_t r, uint32_t b) {
    return r * 128u + ((((b >> 4) ^ (r & 7u)) & 7u) << 4) + (b & 15u);
}
__device__ __forceinline__ void cp16(uint32_t dst, const void* src, bool v) {
    int sz = v ? 16 : 0;
    asm volatile("cp.async.cg.shared.global [%0], [%1], 16, %2;"
                 :: "r"(dst), "l"(src), "r"(sz) : "memory");
}
#define CP_COMMIT() asm volatile("cp.async.commit_group;" ::: "memory")
#define CP_WAIT1()  asm volatile("cp.async.wait_group 1;" ::: "memory")
#define CP_WAIT0()  asm volatile("cp.async.wait_group 0;" ::: "memory")

#define LDSM_X4(r0, r1, r2, r3, addr) \
    asm volatile("ldmatrix.sync.aligned.m8n8.x4.shared.b16 {%0,%1,%2,%3}, [%4];" \
                 : "=r"(r0), "=r"(r1), "=r"(r2), "=r"(r3) : "r"(addr))

__device__ __forceinline__ void mma16816(float* c, const uint32_t* a, const uint32_t* b) {
    asm("mma.sync.aligned.m16n8k16.row.col.f32.bf16.bf16.f32 "
        "{%0,%1,%2,%3}, {%4,%5,%6,%7}, {%8,%9}, {%0,%1,%2,%3};"
        : "+f"(c[0]), "+f"(c[1]), "+f"(c[2]), "+f"(c[3])
        : "r"(a[0]), "r"(a[1]), "r"(a[2]), "r"(a[3]), "r"(b[0]), "r"(b[1]));
}

// ---------------------------------------------------------------------------
// Split-bf16 tensor-core GEMM: C[M,N] = (Ah+Al)[M,K] * (Bh+Bl)[N,K]^T
// CTA tile 128x128, BK=64 (128B rows, SW128 swizzle), 256 thr, 2-stage cp.async.
// grid = (ceil(N/128), M/128)
// ---------------------------------------------------------------------------
#define STAGE_BYTES 65536
#define GEMM_SMEM   (2 * STAGE_BYTES)   // 131072

__device__ __forceinline__ void stage_load(
    uint32_t sb, const __nv_bfloat16* Ah, const __nv_bfloat16* Al,
    const __nv_bfloat16* Bh, const __nv_bfloat16* Bl,
    int row0, int col0, int lda, int ldb, int rowsB, int kc, int tid)
{
#pragma unroll
    for (int i = 0; i < 4; i++) {
        int idx = tid + i * 256;          // 0..1023
        uint32_t r = idx >> 3;            // row 0..127
        uint32_t c = idx & 7;             // 16B chunk 0..7
        uint32_t doff = swz(r, c * 16);
        size_t aoff = (size_t)(row0 + r) * lda * 2 + (size_t)kc * 128 + c * 16;
        cp16(sb + doff,         (const char*)Ah + aoff, true);
        cp16(sb + 16384 + doff, (const char*)Al + aoff, true);
        bool v = ((int)r < rowsB);
        uint32_t rb = v ? r : 0;
        size_t boff = (size_t)(col0 + rb) * ldb * 2 + (size_t)kc * 128 + c * 16;
        cp16(sb + 32768 + doff, (const char*)Bh + boff, v);
        cp16(sb + 49152 + doff, (const char*)Bl + boff, v);
    }
}

__global__ __launch_bounds__(256) void gemm_mma(
    const __nv_bfloat16* __restrict__ Ah, const __nv_bfloat16* __restrict__ Al,
    const __nv_bfloat16* __restrict__ Bh, const __nv_bfloat16* __restrict__ Bl,
    float* __restrict__ C, int K, int lda, int ldb, int ldc, int Nreal)
{
    extern __shared__ char smem[];
    const uint32_t smem_u = smem_to_u32(smem);
    const int tid  = threadIdx.x;
    const int lane = tid & 31;
    const int wid  = tid >> 5;
    const int wm   = wid & 3;    // 0..3 -> 32 rows each
    const int wn   = wid >> 2;   // 0..1 -> 64 cols each
    const int row0 = blockIdx.y * 128, col0 = blockIdx.x * 128;

    int rowsB = Nreal - col0; if (rowsB > 128) rowsB = 128;
    const int n = K >> 6;

    float acc[2][8][4];
#pragma unroll
    for (int mt = 0; mt < 2; mt++)
#pragma unroll
        for (int nt = 0; nt < 8; nt++)
#pragma unroll
            for (int q = 0; q < 4; q++) acc[mt][nt][q] = 0.f;

    stage_load(smem_u, Ah, Al, Bh, Bl, row0, col0, lda, ldb, rowsB, 0, tid);
    CP_COMMIT();
    if (n > 1) {
        stage_load(smem_u + STAGE_BYTES, Ah, Al, Bh, Bl, row0, col0, lda, ldb, rowsB, 1, tid);
        CP_COMMIT();
    }

    // precomputed intra-tile fragment coordinates
    const uint32_t rA_base = wm * 32 + (lane & 15);
    const uint32_t bA_lane = ((lane >> 4) << 4);
    const uint32_t rB_base = wn * 64 + ((lane >> 4) << 3) + (lane & 7);
    const uint32_t bB_lane = (((lane >> 3) & 1) << 4);

    for (int c2 = 0; c2 < n; c2++) {
        if (c2 + 1 < n) { CP_WAIT1(); } else { CP_WAIT0(); }
        __syncthreads();

        const uint32_t sb = smem_u + (uint32_t)(c2 & 1) * STAGE_BYTES;
#pragma unroll
        for (int ks = 0; ks < 4; ks++) {
            uint32_t ahf[2][4], alf[2][4], bhf[4][4], blf[4][4];
#pragma unroll
            for (int mt = 0; mt < 2; mt++) {
                uint32_t aaddr = sb + swz(rA_base + mt * 16, ks * 32 + bA_lane);
                LDSM_X4(ahf[mt][0], ahf[mt][1], ahf[mt][2], ahf[mt][3], aaddr);
                LDSM_X4(alf[mt][0], alf[mt][1], alf[mt][2], alf[mt][3], aaddr + 16384);
            }
#pragma unroll
            for (int p = 0; p < 4; p++) {
                uint32_t baddr = sb + 32768 + swz(rB_base + p * 16, ks * 32 + bB_lane);
                LDSM_X4(bhf[p][0], bhf[p][1], bhf[p][2], bhf[p][3], baddr);
                LDSM_X4(blf[p][0], blf[p][1], blf[p][2], blf[p][3], baddr + 16384);
            }
#pragma unroll
            for (int mt = 0; mt < 2; mt++)
#pragma unroll
                for (int nt = 0; nt < 8; nt++) {
                    const uint32_t* b2h = &bhf[nt >> 1][(nt & 1) * 2];
                    const uint32_t* b2l = &blf[nt >> 1][(nt & 1) * 2];
                    mma16816(acc[mt][nt], ahf[mt], b2h);
                    mma16816(acc[mt][nt], alf[mt], b2h);
                    mma16816(acc[mt][nt], ahf[mt], b2l);
                }
        }
        __syncthreads();
        if (c2 + 2 < n) {
            stage_load(smem_u + (uint32_t)(c2 & 1) * STAGE_BYTES,
                       Ah, Al, Bh, Bl, row0, col0, lda, ldb, rowsB, c2 + 2, tid);
            CP_COMMIT();
        }
    }

    // epilogue: direct fp32 stores
    const int rr = row0 + wm * 32 + (lane >> 2);
    const int cc = col0 + wn * 64 + (lane & 3) * 2;
#pragma unroll
    for (int mt = 0; mt < 2; mt++)
#pragma unroll
        for (int nt = 0; nt < 8; nt++) {
            int colb = cc + nt * 8;
            if (colb < Nreal) {
                float2 v01 = make_float2(acc[mt][nt][0], acc[mt][nt][1]);
                float2 v23 = make_float2(acc[mt][nt][2], acc[mt][nt][3]);
                *reinterpret_cast<float2*>(&C[(size_t)(rr + mt * 16)     * ldc + colb]) = v01;
                *reinterpret_cast<float2*>(&C[(size_t)(rr + mt * 16 + 8) * ldc + colb]) = v23;
            }
        }
}

// ---------------------------------------------------------------------------
// fp32 -> (hi, lo) bf16 split
// ---------------------------------------------------------------------------
__device__ __forceinline__ void split1(float x, __nv_bfloat16& h, __nv_bfloat16& l) {
    h = __float2bfloat16(x);
    l = __float2bfloat16(x - __bfloat162float(h));
}
__global__ void split_kernel(const float* __restrict__ src,
                             __nv_bfloat16* __restrict__ hi,
                             __nv_bfloat16* __restrict__ lo, int n)
{
    int i = blockIdx.x * blockDim.x + threadIdx.x;
    if (i < n) split1(src[i], hi[i], lo[i]);
}

// ---------------------------------------------------------------------------
// causal depthwise conv (k=4) + bias + silu, fused hi/lo split of output
// ---------------------------------------------------------------------------
__global__ void conv_silu_kernel(const float* __restrict__ XZ,
                                 const float* __restrict__ w,
                                 const float* __restrict__ cb,
                                 float* __restrict__ Xc,
                                 __nv_bfloat16* __restrict__ XcH,
                                 __nv_bfloat16* __restrict__ XcL)
{
    int idx = blockIdx.x * blockDim.x + threadIdx.x;
    if (idx >= NTOK * DI) return;
    int d = idx & (DI - 1);
    int token = idx >> 11;
    int b = token >> 10;
    int l = token & (LL - 1);

    float accv = cb[d];
#pragma unroll
    for (int j = 0; j < 4; j++) {
        int ll = l + j - 3;
        if (ll >= 0)
            accv = fmaf(w[d * 4 + j], XZ[(size_t)(b * LL + ll) * (2 * DI) + d], accv);
    }
    float s = accv / (1.f + expf(-accv));
    Xc[idx] = s;
    split1(s, XcH[idx], XcL[idx]);
}

// ---------------------------------------------------------------------------
__global__ void delta_kernel(float* __restrict__ DT, const float* __restrict__ dt_bias)
{
    int idx = blockIdx.x * blockDim.x + threadIdx.x;
    if (idx >= NTOK * DI) return;
    int d = idx & (DI - 1);
    float v = DT[idx] + dt_bias[d];
    float sp = (v > 30.f) ? v : log1pf(expf(v));
    DT[idx] = fminf(fmaxf(sp, 1e-4f), 20.f);
}

__global__ void beta_kernel(const float* __restrict__ XDBL)
{
    __shared__ float sm[1024];
    float mv = 3.0e38f;
    for (int i = threadIdx.x; i < NTOK * DS; i += 1024) {
        int token = i >> 4, n = i & 15;
        mv = fminf(mv, XDBL[token * XDBLC + DTR + n]);
    }
    sm[threadIdx.x] = mv;
    __syncthreads();
    for (int s = 512; s > 0; s >>= 1) {
        if (threadIdx.x < s) sm[threadIdx.x] = fminf(sm[threadIdx.x], sm[threadIdx.x + s]);
        __syncthreads();
    }
    if (threadIdx.x == 0) g_beta = fmaxf(0.f, -sm[0]);
}

// ---------------------------------------------------------------------------
// selective scan (16 lanes per sequence), fused gating + hi/lo split of Y
// ---------------------------------------------------------------------------
__global__ __launch_bounds__(256) void scan_kernel(
    const float* __restrict__ XZ,   const float* __restrict__ XDBL,
    const float* __restrict__ DELTA,const float* __restrict__ Xc,
    const float* __restrict__ A_log,const float* __restrict__ Dv,
    float* __restrict__ Y,
    __nv_bfloat16* __restrict__ YH, __nv_bfloat16* __restrict__ YL)
{
    int gtid = blockIdx.x * blockDim.x + threadIdx.x;
    int lane = gtid & 31;
    int warp = gtid >> 5;
    int seq  = warp * 2 + (lane >> 4);
    int n    = lane & 15;
    int b    = seq >> 11;
    int d    = seq & (DI - 1);

    float a    = expf(A_log[d * DS + n]);
    float beta = g_beta;
    float Dd   = Dv[d];
    float state = 0.f;
    int tokBase = b << 10;

    for (int l = 0; l < LL; l++) {
        int token = tokBase + l;
        float delta = DELTA[(size_t)token * DI + d];
        float x     = Xc[(size_t)token * DI + d];
        const float* xr = XDBL + (size_t)token * XDBLC;
        float Bv = xr[DTR + n] + beta;
        float Cv = xr[DTR + DS + n];
        float dA = expf(-delta * a);
        state = fmaf(dA, state, (delta * x) * Bv);
        float p = state * Cv;
        p += __shfl_xor_sync(0xffffffffu, p, 1);
        p += __shfl_xor_sync(0xffffffffu, p, 2);
        p += __shfl_xor_sync(0xffffffffu, p, 4);
        p += __shfl_xor_sync(0xffffffffu, p, 8);
        if (n == 0) {
            float z  = XZ[(size_t)token * (2 * DI) + DI + d];
            float sz = z / (1.f + expf(-z));
            float yv = (p + x * Dd) * sz;
            size_t oi = (size_t)token * DI + d;
            Y[oi] = yv;
            split1(yv, YH[oi], YL[oi]);
        }
    }
}

// ---------------------------------------------------------------------------
extern "C" void kernel_launch(void* const* d_in, const int* in_sizes, int n_in,
                              void* d_out, int out_size)
{
    const float* hidden  = (const float*)d_in[0];
    const float* W_in    = (const float*)d_in[1];
    const float* conv_w  = (const float*)d_in[2];
    const float* conv_b  = (const float*)d_in[3];
    const float* W_x     = (const float*)d_in[4];
    const float* W_dt    = (const float*)d_in[5];
    const float* dt_bias = (const float*)d_in[6];
    const float* W_out   = (const float*)d_in[7];
    const float* A_log   = (const float*)d_in[8];
    const float* Dv      = (const float*)d_in[9];
    float* out = (float*)d_out;

    float *XZ, *Xc, *XDBL, *DELTA, *Y;
    cudaGetSymbolAddress((void**)&XZ,    g_XZ);
    cudaGetSymbolAddress((void**)&Xc,    g_Xc);
    cudaGetSymbolAddress((void**)&XDBL,  g_XDBL);
    cudaGetSymbolAddress((void**)&DELTA, g_DELTA);
    cudaGetSymbolAddress((void**)&Y,     g_Y);

    __nv_bfloat16 *hidH,*hidL,*WinH,*WinL,*XcH,*XcL,*WxH,*WxL,*XdH,*XdL,
                  *WdtH,*WdtL,*YH,*YL,*WoutH,*WoutL;
    cudaGetSymbolAddress((void**)&hidH,  g_hidH);  cudaGetSymbolAddress((void**)&hidL,  g_hidL);
    cudaGetSymbolAddress((void**)&WinH,  g_WinH);  cudaGetSymbolAddress((void**)&WinL,  g_WinL);
    cudaGetSymbolAddress((void**)&XcH,   g_XcH);   cudaGetSymbolAddress((void**)&XcL,   g_XcL);
    cudaGetSymbolAddress((void**)&WxH,   g_WxH);   cudaGetSymbolAddress((void**)&WxL,   g_WxL);
    cudaGetSymbolAddress((void**)&XdH,   g_XdH);   cudaGetSymbolAddress((void**)&XdL,   g_XdL);
    cudaGetSymbolAddress((void**)&WdtH,  g_WdtH);  cudaGetSymbolAddress((void**)&WdtL,  g_WdtL);
    cudaGetSymbolAddress((void**)&YH,    g_YH);    cudaGetSymbolAddress((void**)&YL,    g_YL);
    cudaGetSymbolAddress((void**)&WoutH, g_WoutH); cudaGetSymbolAddress((void**)&WoutL, g_WoutL);

    cudaFuncSetAttribute(gemm_mma, cudaFuncAttributeMaxDynamicSharedMemorySize, GEMM_SMEM);

    // splits of inputs
    split_kernel<<<(NTOK*DM + 255)/256, 256>>>(hidden, hidH, hidL, NTOK*DM);
    split_kernel<<<(2*DI*DM + 255)/256, 256>>>(W_in, WinH, WinL, 2*DI*DM);
    split_kernel<<<(XDBLC*DI + 255)/256, 256>>>(W_x, WxH, WxL, XDBLC*DI);
    split_kernel<<<(DI*DTR + 255)/256, 256>>>(W_dt, WdtH, WdtL, DI*DTR);
    split_kernel<<<(DM*DI + 255)/256, 256>>>(W_out, WoutH, WoutL, DM*DI);

    // 1) xz = hidden @ W_in^T   (M=2048, N=4096, K=1024)
    gemm_mma<<<dim3(4096/128, NTOK/128), 256, GEMM_SMEM>>>(
        hidH, hidL, WinH, WinL, XZ, DM, DM, DM, 2*DI, 2*DI);

    // 2) conv + silu (+ split)
    conv_silu_kernel<<<(NTOK*DI)/256, 256>>>(XZ, conv_w, conv_b, Xc, XcH, XcL);

    // 3) x_dbl = Xc @ W_x^T     (M=2048, N=96 pad 128, K=2048)
    gemm_mma<<<dim3(1, NTOK/128), 256, GEMM_SMEM>>>(
        XcH, XcL, WxH, WxL, XDBL, DI, DI, DI, XDBLC, XDBLC);

    // split x_dbl for GEMM4
    split_kernel<<<(NTOK*XDBLC + 255)/256, 256>>>(XDBL, XdH, XdL, NTOK*XDBLC);

    // 4) dt = x_dbl[:, :64] @ W_dt^T  (M=2048, N=2048, K=64; lda=96)
    gemm_mma<<<dim3(DI/128, NTOK/128), 256, GEMM_SMEM>>>(
        XdH, XdL, WdtH, WdtL, DELTA, DTR, XDBLC, DTR, DI, DI);

    // 5) delta
    delta_kernel<<<(NTOK*DI)/256, 256>>>(DELTA, dt_bias);

    // 6) beta
    beta_kernel<<<1, 1024>>>(XDBL);

    // 7) scan (+ gating + split)
    scan_kernel<<<(NB*DI*DS)/256, 256>>>(XZ, XDBL, DELTA, Xc, A_log, Dv, Y, YH, YL);

    // 8) out = Y @ W_out^T      (M=2048, N=1024, K=2048)
    gemm_mma<<<dim3(DM/128, NTOK/128), 256, GEMM_SMEM>>>(
        YH, YL, WoutH, WoutL, out, DI, DI, DI, DM, DM);
}

// round 8
// speedup vs baseline: 4.7183x; 1.7493x over previous
#include <cuda_runtime.h>
#include <cuda_fp16.h>
#include <cstdint>
#include <stdint.h>
#include <math.h>

// ---------------- problem dims (fixed) ----------------
#define DM    1024
#define DI    2048
#define DS    16
#define DTR   64
#define NB    2
#define LL    1024
#define NTOK  (NB*LL)        // 2048
#define XDBLC (DTR + 2*DS)   // 96

// ---------------- fp32 scratch ----------------
__device__ float g_XZ   [NTOK * 2 * DI];
__device__ float g_Xc   [NTOK * DI];
__device__ float g_XDBL [NTOK * XDBLC];
__device__ float g_DELTA[NTOK * DI];
__device__ float g_Y    [NTOK * DI];
__device__ float g_beta;

// ---------------- fp16 scratch (uint4 => 16B aligned) ----------------
__device__ uint4 g_hidH [NTOK*DM/8],   g_hidL [NTOK*DM/8];
__device__ uint4 g_WinH [2*DI*DM/8];
__device__ uint4 g_XcH  [NTOK*DI/8],   g_XcL  [NTOK*DI/8];
__device__ uint4 g_WxH  [XDBLC*DI/8];
__device__ uint4 g_XdH  [NTOK*XDBLC/8],g_XdL  [NTOK*XDBLC/8];
__device__ uint4 g_WdtH [DI*DTR/8];
__device__ uint4 g_YH   [NTOK*DI/8],   g_YL   [NTOK*DI/8];
__device__ uint4 g_WoutH[DM*DI/8];

// ---------------- helpers ----------------
__device__ __forceinline__ uint32_t smem_to_u32(const void* p) {
    uint32_t a;
    asm("{ .reg .u64 t; cvta.to.shared.u64 t, %1; cvt.u32.u64 %0, t; }" : "=r"(a) : "l"(p));
    return a;
}
// SW128-style swizzle inside a 128-rows x 128B tile: row r, byte col b
__device__ __forceinline__ uint32_t swz(uint32_t r, uint32_t b) {
    return r * 128u + ((((b >> 4) ^ (r & 7u)) & 7u) << 4) + (b & 15u);
}
__device__ __forceinline__ void cp16(uint32_t dst, const void* src, bool v) {
    int sz = v ? 16 : 0;
    asm volatile("cp.async.cg.shared.global [%0], [%1], 16, %2;"
                 :: "r"(dst), "l"(src), "r"(sz) : "memory");
}
#define CP_COMMIT() asm volatile("cp.async.commit_group;" ::: "memory")
#define CP_WAIT1()  asm volatile("cp.async.wait_group 1;" ::: "memory")
#define CP_WAIT0()  asm volatile("cp.async.wait_group 0;" ::: "memory")

#define LDSM_X4(r0, r1, r2, r3, addr) \
    asm volatile("ldmatrix.sync.aligned.m8n8.x4.shared.b16 {%0,%1,%2,%3}, [%4];" \
                 : "=r"(r0), "=r"(r1), "=r"(r2), "=r"(r3) : "r"(addr))

__device__ __forceinline__ void mma16816(float* c, const uint32_t* a, const uint32_t* b) {
    asm("mma.sync.aligned.m16n8k16.row.col.f32.f16.f16.f32 "
        "{%0,%1,%2,%3}, {%4,%5,%6,%7}, {%8,%9}, {%0,%1,%2,%3};"
        : "+f"(c[0]), "+f"(c[1]), "+f"(c[2]), "+f"(c[3])
        : "r"(a[0]), "r"(a[1]), "r"(a[2]), "r"(a[3]), "r"(b[0]), "r"(b[1]));
}

// ---------------------------------------------------------------------------
// Split-fp16 tensor-core GEMM: C[M,N] = (Ah+Al)[M,K] * Bh[N,K]^T  (2-pass)
// CTA tile 128x128, BK=64, 256 thr, 2-stage cp.async, 2 CTAs/SM (96KB smem).
// grid = (ceil(N/128), M/128)
// ---------------------------------------------------------------------------
#define STAGE_BYTES 49152
#define GEMM_SMEM   (2 * STAGE_BYTES)   // 98304

__device__ __forceinline__ void stage_load(
    uint32_t sb, const __half* Ah, const __half* Al, const __half* Bh,
    int row0, int col0, int lda, int ldb, int rowsB, int kc, int tid)
{
#pragma unroll
    for (int i = 0; i < 4; i++) {
        int idx = tid + i * 256;          // 0..1023
        uint32_t r = idx >> 3;            // row 0..127
        uint32_t c = idx & 7;             // 16B chunk 0..7
        uint32_t doff = swz(r, c * 16);
        size_t aoff = (size_t)(row0 + r) * lda * 2 + (size_t)kc * 128 + c * 16;
        cp16(sb + doff,         (const char*)Ah + aoff, true);
        cp16(sb + 16384 + doff, (const char*)Al + aoff, true);
        bool v = ((int)r < rowsB);
        uint32_t rb = v ? r : 0;
        size_t boff = (size_t)(col0 + rb) * ldb * 2 + (size_t)kc * 128 + c * 16;
        cp16(sb + 32768 + doff, (const char*)Bh + boff, v);
    }
}

__global__ __launch_bounds__(256, 2) void gemm_mma(
    const __half* __restrict__ Ah, const __half* __restrict__ Al,
    const __half* __restrict__ Bh,
    float* __restrict__ C, int K, int lda, int ldb, int ldc, int Nreal)
{
    extern __shared__ char smem[];
    const uint32_t smem_u = smem_to_u32(smem);
    const int tid  = threadIdx.x;
    const int lane = tid & 31;
    const int wid  = tid >> 5;
    const int wm   = wid & 3;    // 0..3 -> 32 rows each
    const int wn   = wid >> 2;   // 0..1 -> 64 cols each
    const int row0 = blockIdx.y * 128, col0 = blockIdx.x * 128;

    int rowsB = Nreal - col0; if (rowsB > 128) rowsB = 128;
    const int n = K >> 6;

    float acc[2][8][4];
#pragma unroll
    for (int mt = 0; mt < 2; mt++)
#pragma unroll
        for (int nt = 0; nt < 8; nt++)
#pragma unroll
            for (int q = 0; q < 4; q++) acc[mt][nt][q] = 0.f;

    stage_load(smem_u, Ah, Al, Bh, row0, col0, lda, ldb, rowsB, 0, tid);
    CP_COMMIT();
    if (n > 1) {
        stage_load(smem_u + STAGE_BYTES, Ah, Al, Bh, row0, col0, lda, ldb, rowsB, 1, tid);
        CP_COMMIT();
    }

    const uint32_t rA_base = wm * 32 + (lane & 15);
    const uint32_t bA_lane = ((lane >> 4) << 4);
    const uint32_t rB_base = wn * 64 + ((lane >> 4) << 3) + (lane & 7);
    const uint32_t bB_lane = (((lane >> 3) & 1) << 4);

    for (int c2 = 0; c2 < n; c2++) {
        if (c2 + 1 < n) { CP_WAIT1(); } else { CP_WAIT0(); }
        __syncthreads();

        const uint32_t sb = smem_u + (uint32_t)(c2 & 1) * STAGE_BYTES;
#pragma unroll
        for (int ks = 0; ks < 4; ks++) {
            uint32_t ahf[2][4], alf[2][4], bhf[4][4];
#pragma unroll
            for (int mt = 0; mt < 2; mt++) {
                uint32_t aaddr = sb + swz(rA_base + mt * 16, ks * 32 + bA_lane);
                LDSM_X4(ahf[mt][0], ahf[mt][1], ahf[mt][2], ahf[mt][3], aaddr);
                LDSM_X4(alf[mt][0], alf[mt][1], alf[mt][2], alf[mt][3], aaddr + 16384);
            }
#pragma unroll
            for (int p = 0; p < 4; p++) {
                uint32_t baddr = sb + 32768 + swz(rB_base + p * 16, ks * 32 + bB_lane);
                LDSM_X4(bhf[p][0], bhf[p][1], bhf[p][2], bhf[p][3], baddr);
            }
#pragma unroll
            for (int mt = 0; mt < 2; mt++)
#pragma unroll
                for (int nt = 0; nt < 8; nt++) {
                    const uint32_t* b2h = &bhf[nt >> 1][(nt & 1) * 2];
                    mma16816(acc[mt][nt], ahf[mt], b2h);
                    mma16816(acc[mt][nt], alf[mt], b2h);
                }
        }
        __syncthreads();
        if (c2 + 2 < n) {
            stage_load(smem_u + (uint32_t)(c2 & 1) * STAGE_BYTES,
                       Ah, Al, Bh, row0, col0, lda, ldb, rowsB, c2 + 2, tid);
            CP_COMMIT();
        }
    }

    // epilogue: direct fp32 stores
    const int rr = row0 + wm * 32 + (lane >> 2);
    const int cc = col0 + wn * 64 + (lane & 3) * 2;
#pragma unroll
    for (int mt = 0; mt < 2; mt++)
#pragma unroll
        for (int nt = 0; nt < 8; nt++) {
            int colb = cc + nt * 8;
            if (colb < Nreal) {
                float2 v01 = make_float2(acc[mt][nt][0], acc[mt][nt][1]);
                float2 v23 = make_float2(acc[mt][nt][2], acc[mt][nt][3]);
                *reinterpret_cast<float2*>(&C[(size_t)(rr + mt * 16)     * ldc + colb]) = v01;
                *reinterpret_cast<float2*>(&C[(size_t)(rr + mt * 16 + 8) * ldc + colb]) = v23;
            }
        }
}

// ---------------------------------------------------------------------------
// fp32 -> fp16 hi/lo split helpers
// ---------------------------------------------------------------------------
__device__ __forceinline__ void split1(float x, __half& h, __half& l) {
    h = __float2half_rn(x);
    l = __float2half_rn(x - __half2float(h));
}
__global__ void splitHL_kernel(const float* __restrict__ src,
                               __half* __restrict__ hi,
                               __half* __restrict__ lo, int n)
{
    int i = blockIdx.x * blockDim.x + threadIdx.x;
    if (i < n) split1(src[i], hi[i], lo[i]);
}
__global__ void splitH_kernel(const float* __restrict__ src,
                              __half* __restrict__ hi, int n)
{
    int i = blockIdx.x * blockDim.x + threadIdx.x;
    if (i < n) hi[i] = __float2half_rn(src[i]);
}

// ---------------------------------------------------------------------------
// causal depthwise conv (k=4) + bias + silu, fused hi/lo split of output
// ---------------------------------------------------------------------------
__global__ void conv_silu_kernel(const float* __restrict__ XZ,
                                 const float* __restrict__ w,
                                 const float* __restrict__ cb,
                                 float* __restrict__ Xc,
                                 __half* __restrict__ XcH,
                                 __half* __restrict__ XcL)
{
    int idx = blockIdx.x * blockDim.x + threadIdx.x;
    if (idx >= NTOK * DI) return;
    int d = idx & (DI - 1);
    int token = idx >> 11;
    int b = token >> 10;
    int l = token & (LL - 1);

    float accv = cb[d];
#pragma unroll
    for (int j = 0; j < 4; j++) {
        int ll = l + j - 3;
        if (ll >= 0)
            accv = fmaf(w[d * 4 + j], XZ[(size_t)(b * LL + ll) * (2 * DI) + d], accv);
    }
    float s = __fdividef(accv, 1.f + __expf(-accv));
    Xc[idx] = s;
    split1(s, XcH[idx], XcL[idx]);
}

// ---------------------------------------------------------------------------
__global__ void delta_kernel(float* __restrict__ DT, const float* __restrict__ dt_bias)
{
    int idx = blockIdx.x * blockDim.x + threadIdx.x;
    if (idx >= NTOK * DI) return;
    int d = idx & (DI - 1);
    float v = DT[idx] + dt_bias[d];
    float sp = (v > 20.f) ? v : __logf(1.f + __expf(v));
    DT[idx] = fminf(fmaxf(sp, 1e-4f), 20.f);
}

__global__ void beta_kernel(const float* __restrict__ XDBL)
{
    __shared__ float sm[1024];
    float mv = 3.0e38f;
    for (int i = threadIdx.x; i < NTOK * DS; i += 1024) {
        int token = i >> 4, n = i & 15;
        mv = fminf(mv, XDBL[token * XDBLC + DTR + n]);
    }
    sm[threadIdx.x] = mv;
    __syncthreads();
    for (int s = 512; s > 0; s >>= 1) {
        if (threadIdx.x < s) sm[threadIdx.x] = fminf(sm[threadIdx.x], sm[threadIdx.x + s]);
        __syncthreads();
    }
    if (threadIdx.x == 0) g_beta = fmaxf(0.f, -sm[0]);
}

// ---------------------------------------------------------------------------
// selective scan (16 lanes per sequence), prefetch-1 pipelined,
// fused gating + hi/lo split of Y
// ---------------------------------------------------------------------------
__global__ __launch_bounds__(256) void scan_kernel(
    const float* __restrict__ XZ,   const float* __restrict__ XDBL,
    const float* __restrict__ DELTA,const float* __restrict__ Xc,
    const float* __restrict__ A_log,const float* __restrict__ Dv,
    float* __restrict__ Y,
    __half* __restrict__ YH, __half* __restrict__ YL)
{
    int gtid = blockIdx.x * blockDim.x + threadIdx.x;
    int lane = gtid & 31;
    int warp = gtid >> 5;
    int seq  = warp * 2 + (lane >> 4);
    int n    = lane & 15;
    int b    = seq >> 11;
    int d    = seq & (DI - 1);

    float a    = __expf(A_log[d * DS + n]);
    float beta = g_beta;
    float Dd   = Dv[d];
    float state = 0.f;
    int token = b << 10;

    // prefetch l=0
    float dltN = DELTA[(size_t)token * DI + d];
    float xxN  = Xc[(size_t)token * DI + d];
    float BmN  = XDBL[(size_t)token * XDBLC + DTR + n];
    float CmN  = XDBL[(size_t)token * XDBLC + DTR + DS + n];
    float zzN  = XZ[(size_t)token * (2 * DI) + DI + d];

    for (int l = 0; l < LL; l++) {
        float dlt = dltN, xx = xxN, Bm = BmN, Cm = CmN, zz = zzN;
        if (l + 1 < LL) {
            int t2 = token + 1;
            dltN = DELTA[(size_t)t2 * DI + d];
            xxN  = Xc[(size_t)t2 * DI + d];
            BmN  = XDBL[(size_t)t2 * XDBLC + DTR + n];
            CmN  = XDBL[(size_t)t2 * XDBLC + DTR + DS + n];
            zzN  = XZ[(size_t)t2 * (2 * DI) + DI + d];
        }
        float dA = __expf(-dlt * a);
        state = fmaf(dA, state, (dlt * xx) * (Bm + beta));
        float p = state * Cm;
        p += __shfl_xor_sync(0xffffffffu, p, 1);
        p += __shfl_xor_sync(0xffffffffu, p, 2);
        p += __shfl_xor_sync(0xffffffffu, p, 4);
        p += __shfl_xor_sync(0xffffffffu, p, 8);
        if (n == 0) {
            float sz = __fdividef(zz, 1.f + __expf(-zz));
            float yv = (p + xx * Dd) * sz;
            size_t oi = (size_t)token * DI + d;
            Y[oi] = yv;
            split1(yv, YH[oi], YL[oi]);
        }
        token++;
    }
}

// ---------------------------------------------------------------------------
extern "C" void kernel_launch(void* const* d_in, const int* in_sizes, int n_in,
                              void* d_out, int out_size)
{
    const float* hidden  = (const float*)d_in[0];
    const float* W_in    = (const float*)d_in[1];
    const float* conv_w  = (const float*)d_in[2];
    const float* conv_b  = (const float*)d_in[3];
    const float* W_x     = (const float*)d_in[4];
    const float* W_dt    = (const float*)d_in[5];
    const float* dt_bias = (const float*)d_in[6];
    const float* W_out   = (const float*)d_in[7];
    const float* A_log   = (const float*)d_in[8];
    const float* Dv      = (const float*)d_in[9];
    float* out = (float*)d_out;

    float *XZ, *Xc, *XDBL, *DELTA, *Y;
    cudaGetSymbolAddress((void**)&XZ,    g_XZ);
    cudaGetSymbolAddress((void**)&Xc,    g_Xc);
    cudaGetSymbolAddress((void**)&XDBL,  g_XDBL);
    cudaGetSymbolAddress((void**)&DELTA, g_DELTA);
    cudaGetSymbolAddress((void**)&Y,     g_Y);

    __half *hidH,*hidL,*WinH,*XcH,*XcL,*WxH,*XdH,*XdL,*WdtH,*YH,*YL,*WoutH;
    cudaGetSymbolAddress((void**)&hidH,  g_hidH);  cudaGetSymbolAddress((void**)&hidL,  g_hidL);
    cudaGetSymbolAddress((void**)&WinH,  g_WinH);
    cudaGetSymbolAddress((void**)&XcH,   g_XcH);   cudaGetSymbolAddress((void**)&XcL,   g_XcL);
    cudaGetSymbolAddress((void**)&WxH,   g_WxH);
    cudaGetSymbolAddress((void**)&XdH,   g_XdH);   cudaGetSymbolAddress((void**)&XdL,   g_XdL);
    cudaGetSymbolAddress((void**)&WdtH,  g_WdtH);
    cudaGetSymbolAddress((void**)&YH,    g_YH);    cudaGetSymbolAddress((void**)&YL,    g_YL);
    cudaGetSymbolAddress((void**)&WoutH, g_WoutH);

    cudaFuncSetAttribute(gemm_mma, cudaFuncAttributeMaxDynamicSharedMemorySize, GEMM_SMEM);

    // splits of inputs (activations hi/lo, weights hi only)
    splitHL_kernel<<<(NTOK*DM + 255)/256, 256>>>(hidden, hidH, hidL, NTOK*DM);
    splitH_kernel<<<(2*DI*DM + 255)/256, 256>>>(W_in, WinH, 2*DI*DM);
    splitH_kernel<<<(XDBLC*DI + 255)/256, 256>>>(W_x, WxH, XDBLC*DI);
    splitH_kernel<<<(DI*DTR + 255)/256, 256>>>(W_dt, WdtH, DI*DTR);
    splitH_kernel<<<(DM*DI + 255)/256, 256>>>(W_out, WoutH, DM*DI);

    // 1) xz = hidden @ W_in^T   (M=2048, N=4096, K=1024)
    gemm_mma<<<dim3(4096/128, NTOK/128), 256, GEMM_SMEM>>>(
        hidH, hidL, WinH, XZ, DM, DM, DM, 2*DI, 2*DI);

    // 2) conv + silu (+ split)
    conv_silu_kernel<<<(NTOK*DI)/256, 256>>>(XZ, conv_w, conv_b, Xc, XcH, XcL);

    // 3) x_dbl = Xc @ W_x^T     (M=2048, N=96 pad 128, K=2048)
    gemm_mma<<<dim3(1, NTOK/128), 256, GEMM_SMEM>>>(
        XcH, XcL, WxH, XDBL, DI, DI, DI, XDBLC, XDBLC);

    // split x_dbl for GEMM4
    splitHL_kernel<<<(NTOK*XDBLC + 255)/256, 256>>>(XDBL, XdH, XdL, NTOK*XDBLC);

    // 4) dt = x_dbl[:, :64] @ W_dt^T  (M=2048, N=2048, K=64; lda=96)
    gemm_mma<<<dim3(DI/128, NTOK/128), 256, GEMM_SMEM>>>(
        XdH, XdL, WdtH, DELTA, DTR, XDBLC, DTR, DI, DI);

    // 5) delta
    delta_kernel<<<(NTOK*DI)/256, 256>>>(DELTA, dt_bias);

    // 6) beta
    beta_kernel<<<1, 1024>>>(XDBL);

    // 7) scan (+ gating + split)
    scan_kernel<<<(NB*DI*DS)/256, 256>>>(XZ, XDBL, DELTA, Xc, A_log, Dv, Y, YH, YL);

    // 8) out = Y @ W_out^T      (M=2048, N=1024, K=2048)
    gemm_mma<<<dim3(DM/128, NTOK/128), 256, GEMM_SMEM>>>(
        YH, YL, WoutH, out, DI, DI, DI, DM, DM);
}

// round 9
// speedup vs baseline: 7.8104x; 1.6553x over previous
#include <cuda_runtime.h>
#include <cuda_fp16.h>
#include <cstdint>
#include <stdint.h>
#include <math.h>

// ---------------- problem dims (fixed) ----------------
#define DM    1024
#define DI    2048
#define DS    16
#define DTR   64
#define NB    2
#define LL    1024
#define NTOK  (NB*LL)        // 2048
#define XDBLC (DTR + 2*DS)   // 96

// ---------------- fp32 scratch ----------------
__device__ float g_XZ   [NTOK * 2 * DI];
__device__ float g_Xc   [NTOK * DI];
__device__ float g_XDBL [NTOK * XDBLC];
__device__ float g_DELTA[NTOK * DI];
__device__ float g_Y    [NTOK * DI];
__device__ float g_beta;

// ---------------- fp16 scratch (uint4 => 16B aligned) ----------------
__device__ uint4 g_hidH [NTOK*DM/8],   g_hidL [NTOK*DM/8];
__device__ uint4 g_WinH [2*DI*DM/8];
__device__ uint4 g_XcH  [NTOK*DI/8],   g_XcL  [NTOK*DI/8];
__device__ uint4 g_WxH  [XDBLC*DI/8];
__device__ uint4 g_XdH  [NTOK*XDBLC/8],g_XdL  [NTOK*XDBLC/8];
__device__ uint4 g_WdtH [DI*DTR/8];
__device__ uint4 g_YH   [NTOK*DI/8],   g_YL   [NTOK*DI/8];
__device__ uint4 g_WoutH[DM*DI/8];

// ---------------- helpers ----------------
__device__ __forceinline__ uint32_t smem_to_u32(const void* p) {
    uint32_t a;
    asm("{ .reg .u64 t; cvta.to.shared.u64 t, %1; cvt.u32.u64 %0, t; }" : "=r"(a) : "l"(p));
    return a;
}
// SW128-style swizzle inside a 128-rows x 128B tile: row r, byte col b
__device__ __forceinline__ uint32_t swz(uint32_t r, uint32_t b) {
    return r * 128u + ((((b >> 4) ^ (r & 7u)) & 7u) << 4) + (b & 15u);
}
__device__ __forceinline__ void cp16(uint32_t dst, const void* src, bool v) {
    int sz = v ? 16 : 0;
    asm volatile("cp.async.cg.shared.global [%0], [%1], 16, %2;"
                 :: "r"(dst), "l"(src), "r"(sz) : "memory");
}
#define CP_COMMIT() asm volatile("cp.async.commit_group;" ::: "memory")
#define CP_WAIT1()  asm volatile("cp.async.wait_group 1;" ::: "memory")
#define CP_WAIT0()  asm volatile("cp.async.wait_group 0;" ::: "memory")

#define LDSM_X4(r0, r1, r2, r3, addr) \
    asm volatile("ldmatrix.sync.aligned.m8n8.x4.shared.b16 {%0,%1,%2,%3}, [%4];" \
                 : "=r"(r0), "=r"(r1), "=r"(r2), "=r"(r3) : "r"(addr))

__device__ __forceinline__ void mma16816(float* c, const uint32_t* a, const uint32_t* b) {
    asm("mma.sync.aligned.m16n8k16.row.col.f32.f16.f16.f32 "
        "{%0,%1,%2,%3}, {%4,%5,%6,%7}, {%8,%9}, {%0,%1,%2,%3};"
        : "+f"(c[0]), "+f"(c[1]), "+f"(c[2]), "+f"(c[3])
        : "r"(a[0]), "r"(a[1]), "r"(a[2]), "r"(a[3]), "r"(b[0]), "r"(b[1]));
}

// ---------------------------------------------------------------------------
// Split-fp16 tensor-core GEMM with optional split-K (blockIdx.z) + atomic epi.
// C[M,N] (+)= (Ah+Al)[M,K-slice] * Bh[N,K-slice]^T
// CTA tile 128x128, BK=64, 256 thr, 2-stage cp.async, 2 CTAs/SM (96KB smem).
// grid = (ceil(N/128), M/128, ksplit)
// ---------------------------------------------------------------------------
#define STAGE_BYTES 49152
#define GEMM_SMEM   (2 * STAGE_BYTES)   // 98304

__device__ __forceinline__ void stage_load(
    uint32_t sb, const __half* Ah, const __half* Al, const __half* Bh,
    int row0, int col0, int lda, int ldb, int rowsB, int kc, int tid)
{
#pragma unroll
    for (int i = 0; i < 4; i++) {
        int idx = tid + i * 256;          // 0..1023
        uint32_t r = idx >> 3;            // row 0..127
        uint32_t c = idx & 7;             // 16B chunk 0..7
        uint32_t doff = swz(r, c * 16);
        size_t aoff = (size_t)(row0 + r) * lda * 2 + (size_t)kc * 128 + c * 16;
        cp16(sb + doff,         (const char*)Ah + aoff, true);
        cp16(sb + 16384 + doff, (const char*)Al + aoff, true);
        bool v = ((int)r < rowsB);
        uint32_t rb = v ? r : 0;
        size_t boff = (size_t)(col0 + rb) * ldb * 2 + (size_t)kc * 128 + c * 16;
        cp16(sb + 32768 + doff, (const char*)Bh + boff, v);
    }
}

__global__ __launch_bounds__(256, 2) void gemm_mma(
    const __half* __restrict__ Ah, const __half* __restrict__ Al,
    const __half* __restrict__ Bh,
    float* __restrict__ C, int kcn, int lda, int ldb, int ldc, int Nreal,
    int accum)
{
    extern __shared__ char smem[];
    const uint32_t smem_u = smem_to_u32(smem);
    const int tid  = threadIdx.x;
    const int lane = tid & 31;
    const int wid  = tid >> 5;
    const int wm   = wid & 3;    // 0..3 -> 32 rows each
    const int wn   = wid >> 2;   // 0..1 -> 64 cols each
    const int row0 = blockIdx.y * 128, col0 = blockIdx.x * 128;
    const int kc0  = blockIdx.z * kcn;

    int rowsB = Nreal - col0; if (rowsB > 128) rowsB = 128;

    float acc[2][8][4];
#pragma unroll
    for (int mt = 0; mt < 2; mt++)
#pragma unroll
        for (int nt = 0; nt < 8; nt++)
#pragma unroll
            for (int q = 0; q < 4; q++) acc[mt][nt][q] = 0.f;

    stage_load(smem_u, Ah, Al, Bh, row0, col0, lda, ldb, rowsB, kc0, tid);
    CP_COMMIT();
    if (kcn > 1) {
        stage_load(smem_u + STAGE_BYTES, Ah, Al, Bh, row0, col0, lda, ldb, rowsB, kc0 + 1, tid);
        CP_COMMIT();
    }

    const uint32_t rA_base = wm * 32 + (lane & 15);
    const uint32_t bA_lane = ((lane >> 4) << 4);
    const uint32_t rB_base = wn * 64 + ((lane >> 4) << 3) + (lane & 7);
    const uint32_t bB_lane = (((lane >> 3) & 1) << 4);

    for (int c2 = 0; c2 < kcn; c2++) {
        if (c2 + 1 < kcn) { CP_WAIT1(); } else { CP_WAIT0(); }
        __syncthreads();

        const uint32_t sb = smem_u + (uint32_t)(c2 & 1) * STAGE_BYTES;
#pragma unroll
        for (int ks = 0; ks < 4; ks++) {
            uint32_t ahf[2][4], alf[2][4], bhf[4][4];
#pragma unroll
            for (int mt = 0; mt < 2; mt++) {
                uint32_t aaddr = sb + swz(rA_base + mt * 16, ks * 32 + bA_lane);
                LDSM_X4(ahf[mt][0], ahf[mt][1], ahf[mt][2], ahf[mt][3], aaddr);
                LDSM_X4(alf[mt][0], alf[mt][1], alf[mt][2], alf[mt][3], aaddr + 16384);
            }
#pragma unroll
            for (int p = 0; p < 4; p++) {
                uint32_t baddr = sb + 32768 + swz(rB_base + p * 16, ks * 32 + bB_lane);
                LDSM_X4(bhf[p][0], bhf[p][1], bhf[p][2], bhf[p][3], baddr);
            }
#pragma unroll
            for (int mt = 0; mt < 2; mt++)
#pragma unroll
                for (int nt = 0; nt < 8; nt++) {
                    const uint32_t* b2h = &bhf[nt >> 1][(nt & 1) * 2];
                    mma16816(acc[mt][nt], ahf[mt], b2h);
                    mma16816(acc[mt][nt], alf[mt], b2h);
                }
        }
        __syncthreads();
        if (c2 + 2 < kcn) {
            stage_load(smem_u + (uint32_t)(c2 & 1) * STAGE_BYTES,
                       Ah, Al, Bh, row0, col0, lda, ldb, rowsB, kc0 + c2 + 2, tid);
            CP_COMMIT();
        }
    }

    // epilogue
    const int rr = row0 + wm * 32 + (lane >> 2);
    const int cc = col0 + wn * 64 + (lane & 3) * 2;
#pragma unroll
    for (int mt = 0; mt < 2; mt++)
#pragma unroll
        for (int nt = 0; nt < 8; nt++) {
            int colb = cc + nt * 8;
            if (colb < Nreal) {
                float* p0 = &C[(size_t)(rr + mt * 16)     * ldc + colb];
                float* p1 = &C[(size_t)(rr + mt * 16 + 8) * ldc + colb];
                if (accum) {
                    atomicAdd(p0,     acc[mt][nt][0]);
                    atomicAdd(p0 + 1, acc[mt][nt][1]);
                    atomicAdd(p1,     acc[mt][nt][2]);
                    atomicAdd(p1 + 1, acc[mt][nt][3]);
                } else {
                    *reinterpret_cast<float2*>(p0) = make_float2(acc[mt][nt][0], acc[mt][nt][1]);
                    *reinterpret_cast<float2*>(p1) = make_float2(acc[mt][nt][2], acc[mt][nt][3]);
                }
            }
        }
}

// ---------------------------------------------------------------------------
// fp32 -> fp16 hi/lo split helpers + zero
// ---------------------------------------------------------------------------
__device__ __forceinline__ void split1(float x, __half& h, __half& l) {
    h = __float2half_rn(x);
    l = __float2half_rn(x - __half2float(h));
}
__global__ void splitHL_kernel(const float* __restrict__ src,
                               __half* __restrict__ hi,
                               __half* __restrict__ lo, int n)
{
    int i = blockIdx.x * blockDim.x + threadIdx.x;
    if (i < n) split1(src[i], hi[i], lo[i]);
}
__global__ void splitH_kernel(const float* __restrict__ src,
                              __half* __restrict__ hi, int n)
{
    int i = blockIdx.x * blockDim.x + threadIdx.x;
    if (i < n) hi[i] = __float2half_rn(src[i]);
}
__global__ void zero_kernel(float4* __restrict__ p, int n4)
{
    int i = blockIdx.x * blockDim.x + threadIdx.x;
    if (i < n4) p[i] = make_float4(0.f, 0.f, 0.f, 0.f);
}

// ---------------------------------------------------------------------------
// causal depthwise conv (k=4) + bias + silu, fused hi/lo split of output
// ---------------------------------------------------------------------------
__global__ void conv_silu_kernel(const float* __restrict__ XZ,
                                 const float* __restrict__ w,
                                 const float* __restrict__ cb,
                                 float* __restrict__ Xc,
                                 __half* __restrict__ XcH,
                                 __half* __restrict__ XcL)
{
    int idx = blockIdx.x * blockDim.x + threadIdx.x;
    if (idx >= NTOK * DI) return;
    int d = idx & (DI - 1);
    int token = idx >> 11;
    int b = token >> 10;
    int l = token & (LL - 1);

    float accv = cb[d];
#pragma unroll
    for (int j = 0; j < 4; j++) {
        int ll = l + j - 3;
        if (ll >= 0)
            accv = fmaf(w[d * 4 + j], XZ[(size_t)(b * LL + ll) * (2 * DI) + d], accv);
    }
    float s = __fdividef(accv, 1.f + __expf(-accv));
    Xc[idx] = s;
    split1(s, XcH[idx], XcL[idx]);
}

// ---------------------------------------------------------------------------
__global__ void delta_kernel(float* __restrict__ DT, const float* __restrict__ dt_bias)
{
    int idx = blockIdx.x * blockDim.x + threadIdx.x;
    if (idx >= NTOK * DI) return;
    int d = idx & (DI - 1);
    float v = DT[idx] + dt_bias[d];
    float sp = (v > 20.f) ? v : __logf(1.f + __expf(v));
    DT[idx] = fminf(fmaxf(sp, 1e-4f), 20.f);
}

__global__ void beta_kernel(const float* __restrict__ XDBL)
{
    __shared__ float sm[1024];
    float mv = 3.0e38f;
    for (int i = threadIdx.x; i < NTOK * DS; i += 1024) {
        int token = i >> 4, n = i & 15;
        mv = fminf(mv, XDBL[token * XDBLC + DTR + n]);
    }
    sm[threadIdx.x] = mv;
    __syncthreads();
    for (int s = 512; s > 0; s >>= 1) {
        if (threadIdx.x < s) sm[threadIdx.x] = fminf(sm[threadIdx.x], sm[threadIdx.x + s]);
        __syncthreads();
    }
    if (threadIdx.x == 0) g_beta = fmaxf(0.f, -sm[0]);
}

// ---------------------------------------------------------------------------
// selective scan (16 lanes per sequence), unroll-4 with group prefetch,
// fused gating + hi/lo split of Y
// ---------------------------------------------------------------------------
#define UNR 4
__global__ __launch_bounds__(256) void scan_kernel(
    const float* __restrict__ XZ,   const float* __restrict__ XDBL,
    const float* __restrict__ DELTA,const float* __restrict__ Xc,
    const float* __restrict__ A_log,const float* __restrict__ Dv,
    float* __restrict__ Y,
    __half* __restrict__ YH, __half* __restrict__ YL)
{
    int gtid = blockIdx.x * blockDim.x + threadIdx.x;
    int lane = gtid & 31;
    int warp = gtid >> 5;
    int seq  = warp * 2 + (lane >> 4);
    int n    = lane & 15;
    int b    = seq >> 11;
    int d    = seq & (DI - 1);

    float a    = __expf(A_log[d * DS + n]);
    float beta = g_beta;
    float Dd   = Dv[d];
    float state = 0.f;
    const int tok0 = b << 10;

    float dc[UNR], xc[UNR], Bc[UNR], Cc[UNR], zc[UNR];
#pragma unroll
    for (int u = 0; u < UNR; u++) {
        int t = tok0 + u;
        dc[u] = DELTA[(size_t)t * DI + d];
        xc[u] = Xc[(size_t)t * DI + d];
        Bc[u] = XDBL[(size_t)t * XDBLC + DTR + n];
        Cc[u] = XDBL[(size_t)t * XDBLC + DTR + DS + n];
        zc[u] = XZ[(size_t)t * (2 * DI) + DI + d];
    }

    for (int g = 0; g < LL / UNR; g++) {
        float dn[UNR], xn[UNR], Bn[UNR], Cn[UNR], zn[UNR];
        const int tnext = tok0 + (g + 1) * UNR;
        if (g + 1 < LL / UNR) {
#pragma unroll
            for (int u = 0; u < UNR; u++) {
                int t = tnext + u;
                dn[u] = DELTA[(size_t)t * DI + d];
                xn[u] = Xc[(size_t)t * DI + d];
                Bn[u] = XDBL[(size_t)t * XDBLC + DTR + n];
                Cn[u] = XDBL[(size_t)t * XDBLC + DTR + DS + n];
                zn[u] = XZ[(size_t)t * (2 * DI) + DI + d];
            }
        }
#pragma unroll
        for (int u = 0; u < UNR; u++) {
            float dA = __expf(-dc[u] * a);
            state = fmaf(dA, state, (dc[u] * xc[u]) * (Bc[u] + beta));
            float p = state * Cc[u];
            p += __shfl_xor_sync(0xffffffffu, p, 1);
            p += __shfl_xor_sync(0xffffffffu, p, 2);
            p += __shfl_xor_sync(0xffffffffu, p, 4);
            p += __shfl_xor_sync(0xffffffffu, p, 8);
            if (n == 0) {
                float zz = zc[u];
                float sz = __fdividef(zz, 1.f + __expf(-zz));
                float yv = (p + xc[u] * Dd) * sz;
                size_t oi = (size_t)(tok0 + g * UNR + u) * DI + d;
                Y[oi] = yv;
                split1(yv, YH[oi], YL[oi]);
            }
        }
#pragma unroll
        for (int u = 0; u < UNR; u++) {
            dc[u] = dn[u]; xc[u] = xn[u]; Bc[u] = Bn[u]; Cc[u] = Cn[u]; zc[u] = zn[u];
        }
    }
}

// ---------------------------------------------------------------------------
extern "C" void kernel_launch(void* const* d_in, const int* in_sizes, int n_in,
                              void* d_out, int out_size)
{
    const float* hidden  = (const float*)d_in[0];
    const float* W_in    = (const float*)d_in[1];
    const float* conv_w  = (const float*)d_in[2];
    const float* conv_b  = (const float*)d_in[3];
    const float* W_x     = (const float*)d_in[4];
    const float* W_dt    = (const float*)d_in[5];
    const float* dt_bias = (const float*)d_in[6];
    const float* W_out   = (const float*)d_in[7];
    const float* A_log   = (const float*)d_in[8];
    const float* Dv      = (const float*)d_in[9];
    float* out = (float*)d_out;

    float *XZ, *Xc, *XDBL, *DELTA, *Y;
    cudaGetSymbolAddress((void**)&XZ,    g_XZ);
    cudaGetSymbolAddress((void**)&Xc,    g_Xc);
    cudaGetSymbolAddress((void**)&XDBL,  g_XDBL);
    cudaGetSymbolAddress((void**)&DELTA, g_DELTA);
    cudaGetSymbolAddress((void**)&Y,     g_Y);

    __half *hidH,*hidL,*WinH,*XcH,*XcL,*WxH,*XdH,*XdL,*WdtH,*YH,*YL,*WoutH;
    cudaGetSymbolAddress((void**)&hidH,  g_hidH);  cudaGetSymbolAddress((void**)&hidL,  g_hidL);
    cudaGetSymbolAddress((void**)&WinH,  g_WinH);
    cudaGetSymbolAddress((void**)&XcH,   g_XcH);   cudaGetSymbolAddress((void**)&XcL,   g_XcL);
    cudaGetSymbolAddress((void**)&WxH,   g_WxH);
    cudaGetSymbolAddress((void**)&XdH,   g_XdH);   cudaGetSymbolAddress((void**)&XdL,   g_XdL);
    cudaGetSymbolAddress((void**)&WdtH,  g_WdtH);
    cudaGetSymbolAddress((void**)&YH,    g_YH);    cudaGetSymbolAddress((void**)&YL,    g_YL);
    cudaGetSymbolAddress((void**)&WoutH, g_WoutH);

    cudaFuncSetAttribute(gemm_mma, cudaFuncAttributeMaxDynamicSharedMemorySize, GEMM_SMEM);

    // splits of inputs (activations hi/lo, weights hi only)
    splitHL_kernel<<<(NTOK*DM + 255)/256, 256>>>(hidden, hidH, hidL, NTOK*DM);
    splitH_kernel<<<(2*DI*DM + 255)/256, 256>>>(W_in, WinH, 2*DI*DM);
    splitH_kernel<<<(XDBLC*DI + 255)/256, 256>>>(W_x, WxH, XDBLC*DI);
    splitH_kernel<<<(DI*DTR + 255)/256, 256>>>(W_dt, WdtH, DI*DTR);
    splitH_kernel<<<(DM*DI + 255)/256, 256>>>(W_out, WoutH, DM*DI);
    // zero split-K accumulation targets
    zero_kernel<<<(NTOK*XDBLC/4 + 255)/256, 256>>>((float4*)XDBL, NTOK*XDBLC/4);
    zero_kernel<<<(NTOK*DM/4 + 255)/256, 256>>>((float4*)out, NTOK*DM/4);

    // 1) xz = hidden @ W_in^T   (M=2048, N=4096, K=1024)
    gemm_mma<<<dim3(4096/128, NTOK/128, 1), 256, GEMM_SMEM>>>(
        hidH, hidL, WinH, XZ, 16, DM, DM, 2*DI, 2*DI, 0);

    // 2) conv + silu (+ split)
    conv_silu_kernel<<<(NTOK*DI)/256, 256>>>(XZ, conv_w, conv_b, Xc, XcH, XcL);

    // 3) x_dbl = Xc @ W_x^T     (M=2048, N=96 pad 128, K=2048, split-K x4)
    gemm_mma<<<dim3(1, NTOK/128, 4), 256, GEMM_SMEM>>>(
        XcH, XcL, WxH, XDBL, 8, DI, DI, XDBLC, XDBLC, 1);

    // split x_dbl for GEMM4
    splitHL_kernel<<<(NTOK*XDBLC + 255)/256, 256>>>(XDBL, XdH, XdL, NTOK*XDBLC);

    // 4) dt = x_dbl[:, :64] @ W_dt^T  (M=2048, N=2048, K=64; lda=96)
    gemm_mma<<<dim3(DI/128, NTOK/128, 1), 256, GEMM_SMEM>>>(
        XdH, XdL, WdtH, DELTA, 1, XDBLC, DTR, DI, DI, 0);

    // 5) delta
    delta_kernel<<<(NTOK*DI)/256, 256>>>(DELTA, dt_bias);

    // 6) beta
    beta_kernel<<<1, 1024>>>(XDBL);

    // 7) scan (+ gating + split)
    scan_kernel<<<(NB*DI*DS)/256, 256>>>(XZ, XDBL, DELTA, Xc, A_log, Dv, Y, YH, YL);

    // 8) out = Y @ W_out^T      (M=2048, N=1024, K=2048, split-K x2)
    gemm_mma<<<dim3(DM/128, NTOK/128, 2), 256, GEMM_SMEM>>>(
        YH, YL, WoutH, out, 16, DI, DI, DM, DM, 1);
}